// round 15
// baseline (speedup 1.0000x reference)
#include <cuda_runtime.h>
#include <cstdint>

// ---------------------------------------------------------------------------
// D_MPNNLayer on GB300 (sm_103a via compute_103 -> mma.sync, all GEMMs fp16)
// k_edge: 64-edge tiles, 2 CTAs/SM, triple-buffer, dedup-xa epilogue (r14).
// Node GEMMs: fp16, 256 thr, 70KB smem, 2 CTAs/SM (round-12 shape).
// ---------------------------------------------------------------------------

constexpr int NN = 40000;
constexpr int NE = 640000;

constexpr int LDH = 68;                 // f16x2 words per row
constexpr int BW = 128 * LDH;           // 128-row fp16 tile words
constexpr int AW = 64 * LDH;            // 64-row fp16 tile words
constexpr int EDGE_SMEM = (BW + 3 * AW) * 4 + 3 * 512;
constexpr int NODE_SMEM = 2 * BW * 4;   // B + A (128 rows each)

__device__ float g_xab[(size_t)NN * 256];
__device__ float g_mnode[(size_t)NN * 128];
__device__ float g_p[(size_t)NN * 128];

__device__ int g_hist[2 * NN];
__device__ int g_workD[NN], g_workS[NN];
__device__ int g_startD[NN + 8], g_startS[NN + 8];
__device__ int g_bsum[80];
__device__ int g_permD[NE], g_permS[NE];
__device__ int g_sdstD[NE], g_ssrcD[NE];

__device__ __host__ __forceinline__ int permL(int r) {
    return (r & 0x61) | ((r >> 2) & 0x02) | ((r & 0x06) << 1) | (r & 0x10);
}
// edge perm: mma n-index (nt*8+tt*2+k) -> feature (tt*8+nt*2+k)
__device__ __forceinline__ int permE(int r) {
    return (r & 0x60) | (((r >> 1) & 3) << 3) | (((r >> 3) & 3) << 1) | (r & 1);
}

// ---------------- helpers ----------------------------------------------------
__device__ __forceinline__ uint32_t pk_f16x2(float lo, float hi) {
    uint32_t r;
    asm("cvt.rn.f16x2.f32 %0, %1, %2;" : "=r"(r) : "f"(hi), "f"(lo));
    return r;
}
__device__ __forceinline__ void mma16h(float acc[4], uint32_t a0, uint32_t a1, uint32_t a2,
                                       uint32_t a3, uint32_t b0, uint32_t b1) {
    asm("mma.sync.aligned.m16n8k16.row.col.f32.f16.f16.f32 "
        "{%0,%1,%2,%3}, {%4,%5,%6,%7}, {%8,%9}, {%0,%1,%2,%3};"
        : "+f"(acc[0]), "+f"(acc[1]), "+f"(acc[2]), "+f"(acc[3])
        : "r"(a0), "r"(a1), "r"(a2), "r"(a3), "r"(b0), "r"(b1));
}
__device__ __forceinline__ void redv4(float* p, float4 v) {
    asm volatile("red.global.add.v4.f32 [%0], {%1,%2,%3,%4};" ::"l"(p), "f"(v.x), "f"(v.y),
                 "f"(v.z), "f"(v.w)
                 : "memory");
}
// stage one 32-float quarter-row fp32 -> 16 f16x2 words at S + row*LDH + sq*16
__device__ __forceinline__ void stage_quarter_f16(uint32_t* S, int row, int sq,
                                                  const float* __restrict__ gp) {
    uint32_t w[16];
#pragma unroll
    for (int i = 0; i < 8; i++) {
        float4 v = *(const float4*)(gp + i * 4);
        w[2 * i] = pk_f16x2(v.x, v.y);
        w[2 * i + 1] = pk_f16x2(v.z, v.w);
    }
    uint4* dp = (uint4*)(S + row * LDH + sq * 16);
#pragma unroll
    for (int j = 0; j < 4; j++) dp[j] = ((uint4*)w)[j];
}
__device__ __forceinline__ void stage_quarter_zero(uint32_t* S, int row, int sq) {
    uint4* dp = (uint4*)(S + row * LDH + sq * 16);
#pragma unroll
    for (int j = 0; j < 4; j++) dp[j] = make_uint4(0, 0, 0, 0);
}

// fp16 node mma core: 256 thr, warps 4x2 (rows wm*32, cols wn*64), K=128
__device__ __forceinline__ void mma_core_h(const uint32_t* __restrict__ As,
                                           const uint32_t* __restrict__ Bs, int lane,
                                           int wm, int wn, float acc[2][8][4]) {
    int g = lane >> 2, tt = lane & 3;
    const uint32_t* ab = As + (wm * 32 + g) * LDH + tt;
    const uint32_t* bb = Bs + (wn * 64 + g) * LDH + tt;
#pragma unroll
    for (int ks = 0; ks < 8; ks++) {
        int k0 = ks * 8;
        uint32_t b[8][2];
#pragma unroll
        for (int nt = 0; nt < 8; nt++) {
            b[nt][0] = bb[nt * 8 * LDH + k0];
            b[nt][1] = bb[nt * 8 * LDH + k0 + 4];
        }
#pragma unroll
        for (int mt = 0; mt < 2; mt++) {
            uint32_t a0 = ab[(mt * 16 + 0) * LDH + k0];
            uint32_t a1 = ab[(mt * 16 + 8) * LDH + k0];
            uint32_t a2 = ab[(mt * 16 + 0) * LDH + k0 + 4];
            uint32_t a3 = ab[(mt * 16 + 8) * LDH + k0 + 4];
#pragma unroll
            for (int nt = 0; nt < 8; nt++) mma16h(acc[mt][nt], a0, a1, a2, a3, b[nt][0], b[nt][1]);
        }
    }
}

// ---------------- preprocessing -----------------------------------------------
__global__ void k_hist(const int* __restrict__ dst, const int* __restrict__ src) {
    int e = blockIdx.x * 256 + threadIdx.x;
    atomicAdd(&g_hist[dst[e]], 1);
    atomicAdd(&g_hist[NN + src[e]], 1);
}
__global__ void __launch_bounds__(1024) k_scan_local() {
    __shared__ int sc[1024];
    int gy = blockIdx.y, bx = blockIdx.x, tid = threadIdx.x;
    int base = bx * 1000;
    const int* hist = g_hist + gy * NN;
    int* start = gy ? g_startS : g_startD;
    int v = (tid < 1000) ? hist[base + tid] : 0;
    sc[tid] = v;
    __syncthreads();
#pragma unroll
    for (int off = 1; off < 1024; off <<= 1) {
        int t = (tid >= off) ? sc[tid - off] : 0;
        __syncthreads();
        sc[tid] += t;
        __syncthreads();
    }
    if (tid < 1000) start[base + tid] = sc[tid] - v;
    if (tid == 1023) g_bsum[gy * 40 + bx] = sc[1023];
}
__global__ void __launch_bounds__(128) k_scan_bsum() {
    __shared__ int sc[128];
    int tid = threadIdx.x;
    int half = tid >> 6, loc = tid & 63;
    int v = (loc < 40) ? g_bsum[half * 40 + loc] : 0;
    sc[tid] = v;
    __syncthreads();
#pragma unroll
    for (int off = 1; off < 64; off <<= 1) {
        int t = (loc >= off) ? sc[tid - off] : 0;
        __syncthreads();
        sc[tid] += t;
        __syncthreads();
    }
    if (loc < 40) g_bsum[half * 40 + loc] = sc[tid] - v;
    if (loc == 63) {
        if (half == 0) g_startD[NN] = sc[tid];
        else g_startS[NN] = sc[tid];
    }
}
__global__ void __launch_bounds__(1024) k_scan_add() {
    int gy = blockIdx.y, bx = blockIdx.x, tid = threadIdx.x;
    if (tid >= 1000) return;
    int base = bx * 1000;
    int* start = gy ? g_startS : g_startD;
    int* work = gy ? g_workS : g_workD;
    int v = start[base + tid] + g_bsum[gy * 40 + bx];
    start[base + tid] = v;
    work[base + tid] = v;
}
__global__ void k_scatter(const int* __restrict__ dst, const int* __restrict__ src) {
    int e = blockIdx.x * 256 + threadIdx.x;
    int d = dst[e], s = src[e];
    int pd = atomicAdd(&g_workD[d], 1);
    g_permD[pd] = e;
    g_sdstD[pd] = d;
    g_ssrcD[pd] = s;
    int ps = atomicAdd(&g_workS[s], 1);
    g_permS[ps] = e;
}

// ---------------- fp16 node GEMM: xab (per half) -------------------------------
__global__ void __launch_bounds__(256, 2) k_xab_h(const float* __restrict__ x,
                                                  const float* __restrict__ W1) {
    extern __shared__ uint32_t sm[];
    uint32_t* Bs = sm;
    uint32_t* As = sm + BW;
    int tid = threadIdx.x, lane = tid & 31, wid = tid >> 5;
    int wm = wid & 3, wn = wid >> 2;
    int half = blockIdx.y;
    int m0 = blockIdx.x * 128;
    int nrows = NN - m0 < 128 ? NN - m0 : 128;

#pragma unroll
    for (int i = 0; i < 2; i++) {
        int idx = tid + i * 256;
        int r = idx >> 2, q = idx & 3;
        stage_quarter_f16(Bs, r, q, W1 + (size_t)permL(r) * 384 + half * 128 + q * 32);
        if (r < nrows)
            stage_quarter_f16(As, r, q, x + (size_t)(m0 + r) * 128 + q * 32);
        else
            stage_quarter_zero(As, r, q);
    }
    __syncthreads();

    float acc[2][8][4] = {};
    mma_core_h(As, Bs, lane, wm, wn, acc);

    int g = lane >> 2, tt = lane & 3;
#pragma unroll
    for (int mt = 0; mt < 2; mt++)
#pragma unroll
        for (int i = 0; i < 2; i++) {
            int r = m0 + wm * 32 + mt * 16 + g + i * 8;
            if (r < NN) {
                float* op = g_xab + (size_t)r * 256 + half * 128;
#pragma unroll
                for (int nt = 0; nt < 8; nt++) {
                    int col = permL(wn * 64 + nt * 8 + tt * 2);
                    *(float2*)(op + col) =
                        make_float2(acc[mt][nt][2 * i], acc[mt][nt][2 * i + 1]);
                }
            }
        }
}

// ---------------- fp16 node GEMM: p = m_node @ W2^T ----------------------------
__global__ void __launch_bounds__(256, 2) k_p_h(const float* __restrict__ W2) {
    extern __shared__ uint32_t sm[];
    uint32_t* Bs = sm;
    uint32_t* As = sm + BW;
    int tid = threadIdx.x, lane = tid & 31, wid = tid >> 5;
    int wm = wid & 3, wn = wid >> 2;
    int m0 = blockIdx.x * 128;
    int nrows = NN - m0 < 128 ? NN - m0 : 128;

#pragma unroll
    for (int i = 0; i < 2; i++) {
        int idx = tid + i * 256;
        int r = idx >> 2, q = idx & 3;
        stage_quarter_f16(Bs, r, q, W2 + (size_t)r * 128 + q * 32);
        if (r < nrows)
            stage_quarter_f16(As, r, q, g_mnode + (size_t)(m0 + r) * 128 + q * 32);
        else
            stage_quarter_zero(As, r, q);
    }
    __syncthreads();

    float acc[2][8][4] = {};
    mma_core_h(As, Bs, lane, wm, wn, acc);

    int g = lane >> 2, tt = lane & 3;
#pragma unroll
    for (int mt = 0; mt < 2; mt++)
#pragma unroll
        for (int i = 0; i < 2; i++) {
            int r = m0 + wm * 32 + mt * 16 + g + i * 8;
            if (r < NN) {
                float* op = g_p + (size_t)r * 128 + wn * 64 + tt * 2;
#pragma unroll
                for (int nt = 0; nt < 8; nt++)
                    *(float2*)(op + nt * 8) =
                        make_float2(acc[mt][nt][2 * i], acc[mt][nt][2 * i + 1]);
            }
        }
}

// ---------------- edge kernel: 64-edge tiles, 256 thr, 2 CTAs/SM (r14) ---------
__global__ void __launch_bounds__(256, 2) k_edge(const float* __restrict__ h,
                                                 const float* __restrict__ W1) {
    extern __shared__ uint32_t sm[];
    uint32_t* Bs = sm;
    uint32_t* A[3] = {sm + BW, sm + BW + AW, sm + BW + 2 * AW};
    int* idxB = (int*)(sm + BW + 3 * AW);

    int tid = threadIdx.x, lane = tid & 31, wid = tid >> 5;
    int wm = wid & 1, wn = wid >> 1;
    int g = lane >> 2, tt = lane & 3;

    int srow = tid >> 2, sq = tid & 3;
    int sj = ((srow >> 5) << 5) + ((srow & 7) << 2) + ((srow >> 3) & 3);

#pragma unroll
    for (int i = 0; i < 2; i++) {
        int idx = tid + i * 256;
        int r = idx >> 2, q = idx & 3;
        stage_quarter_f16(Bs, r, q, W1 + (size_t)permE(r) * 384 + 256 + q * 32);
    }

    const int G = gridDim.x;
    const int T = (10000 - blockIdx.x + G - 1) / G;

#pragma unroll
    for (int pt = 0; pt < 2; pt++) {
        if (pt < T) {
            int e0 = (blockIdx.x + (size_t)pt * G) * 64;
            int edge = g_permD[e0 + sj];
            stage_quarter_f16(A[pt], srow, sq, h + (size_t)edge * 128 + sq * 32);
            if (tid < 16) ((int4*)(idxB + pt * 128))[tid] = ((const int4*)(g_sdstD + e0))[tid];
            else if (tid < 32)
                ((int4*)(idxB + pt * 128 + 64))[tid - 16] =
                    ((const int4*)(g_ssrcD + e0))[tid - 16];
        }
    }
    __syncthreads();

    int cur = 0;
    for (int t = 0; t < T; t++) {
        bool more2 = (t + 2 < T);
        int nxt2 = cur + 2 >= 3 ? cur - 1 : cur + 2;

        float pf[32];
        int4 pd4 = make_int4(0, 0, 0, 0), ps4 = make_int4(0, 0, 0, 0);
        if (more2) {
            int e0 = (blockIdx.x + (size_t)(t + 2) * G) * 64;
            int edge = g_permD[e0 + sj];
            const float4* hp = (const float4*)(h + (size_t)edge * 128 + sq * 32);
#pragma unroll
            for (int i = 0; i < 8; i++) ((float4*)pf)[i] = hp[i];
            if (tid < 16) pd4 = ((const int4*)(g_sdstD + e0))[tid];
            else if (tid < 32) ps4 = ((const int4*)(g_ssrcD + e0))[tid - 16];
        }

        float acc[2][4][4] = {};
        {
            const uint32_t* ab = A[cur] + (wm * 32 + g) * LDH + tt;
            const uint32_t* bb = Bs + (wn * 32 + g) * LDH + tt;
#pragma unroll
            for (int ks = 0; ks < 8; ks++) {
                int k0 = ks * 8;
                uint32_t b[4][2];
#pragma unroll
                for (int nt = 0; nt < 4; nt++) {
                    b[nt][0] = bb[nt * 8 * LDH + k0];
                    b[nt][1] = bb[nt * 8 * LDH + k0 + 4];
                }
#pragma unroll
                for (int mt = 0; mt < 2; mt++) {
                    uint32_t a0 = ab[(mt * 16 + 0) * LDH + k0];
                    uint32_t a1 = ab[(mt * 16 + 8) * LDH + k0];
                    uint32_t a2 = ab[(mt * 16 + 0) * LDH + k0 + 4];
                    uint32_t a3 = ab[(mt * 16 + 8) * LDH + k0 + 4];
#pragma unroll
                    for (int nt = 0; nt < 4; nt++)
                        mma16h(acc[mt][nt], a0, a1, a2, a3, b[nt][0], b[nt][1]);
                }
            }
        }

        int jb = wm * 32 + 4 * g;
        int4 dd = *(const int4*)(idxB + cur * 128 + jb);
        int4 ss = *(const int4*)(idxB + cur * 128 + 64 + jb);

        if (more2) {
            uint32_t w[16];
#pragma unroll
            for (int j = 0; j < 16; j++) w[j] = pk_f16x2(pf[2 * j], pf[2 * j + 1]);
            uint4* dp = (uint4*)(A[nxt2] + srow * LDH + sq * 16);
#pragma unroll
            for (int j = 0; j < 4; j++) dp[j] = ((uint4*)w)[j];
            if (tid < 16) ((int4*)(idxB + nxt2 * 128))[tid] = pd4;
            else if (tid < 32) ((int4*)(idxB + nxt2 * 128 + 64))[tid - 16] = ps4;
        }

        int col0 = wn * 32 + tt * 8;
        int de[4] = {dd.x, dd.y, dd.z, dd.w};
        int se[4] = {ss.x, ss.y, ss.z, ss.w};
        float4 Bx[4][2];
#pragma unroll
        for (int c = 0; c < 4; c++) {
            const float* xb = g_xab + (size_t)se[c] * 256 + 128 + col0;
            Bx[c][0] = *(const float4*)xb;
            Bx[c][1] = *(const float4*)(xb + 4);
        }
        int curd = de[0];
        const float* xa = g_xab + (size_t)curd * 256 + col0;
        float4 A0 = *(const float4*)xa;
        float4 A1 = *(const float4*)(xa + 4);
        float4 ac0 = make_float4(0.f, 0.f, 0.f, 0.f);
        float4 ac1 = make_float4(0.f, 0.f, 0.f, 0.f);
#pragma unroll
        for (int c = 0; c < 4; c++) {
            if (de[c] != curd) {
                float* mp = g_mnode + (size_t)curd * 128 + col0;
                redv4(mp, ac0);
                redv4(mp + 4, ac1);
                curd = de[c];
                const float* xn = g_xab + (size_t)curd * 256 + col0;
                A0 = *(const float4*)xn;
                A1 = *(const float4*)(xn + 4);
                ac0 = make_float4(0.f, 0.f, 0.f, 0.f);
                ac1 = make_float4(0.f, 0.f, 0.f, 0.f);
            }
            int mt = c >> 1, i2 = (c & 1) * 2;
            ac0.x += fmaxf(acc[mt][0][i2] + A0.x + Bx[c][0].x, 0.f);
            ac0.y += fmaxf(acc[mt][0][i2 + 1] + A0.y + Bx[c][0].y, 0.f);
            ac0.z += fmaxf(acc[mt][1][i2] + A0.z + Bx[c][0].z, 0.f);
            ac0.w += fmaxf(acc[mt][1][i2 + 1] + A0.w + Bx[c][0].w, 0.f);
            ac1.x += fmaxf(acc[mt][2][i2] + A1.x + Bx[c][1].x, 0.f);
            ac1.y += fmaxf(acc[mt][2][i2 + 1] + A1.y + Bx[c][1].y, 0.f);
            ac1.z += fmaxf(acc[mt][3][i2] + A1.z + Bx[c][1].z, 0.f);
            ac1.w += fmaxf(acc[mt][3][i2 + 1] + A1.w + Bx[c][1].w, 0.f);
        }
        {
            float* mp = g_mnode + (size_t)curd * 128 + col0;
            redv4(mp, ac0);
            redv4(mp + 4, ac1);
        }

        cur = (cur + 1 >= 3) ? 0 : cur + 1;
        __syncthreads();
    }
}

// ---------------- LN: warp per node, parallel index/snorm loads ----------------
__global__ void __launch_bounds__(256) k_ln_node(const float* __restrict__ snorm,
                                                 const float* __restrict__ gamma,
                                                 const float* __restrict__ beta,
                                                 float* __restrict__ out) {
    int wid = threadIdx.x >> 5, lane = threadIdx.x & 31;
    int v = blockIdx.x * 8 + wid;
    int beg = g_startS[v], end = g_startS[v + 1];
    if (beg == end) return;

    float4 pv = ((const float4*)(g_p + (size_t)v * 128))[lane];
    float sum = pv.x + pv.y + pv.z + pv.w;
    float ssq = pv.x * pv.x + pv.y * pv.y + pv.z * pv.z + pv.w * pv.w;
#pragma unroll
    for (int o = 16; o > 0; o >>= 1) {
        sum += __shfl_xor_sync(0xffffffffu, sum, o);
        ssq += __shfl_xor_sync(0xffffffffu, ssq, o);
    }
    float mu = sum * 0.0078125f;
    float var = ssq * 0.0078125f - mu * mu;
    float4 gg = ((const float4*)gamma)[lane];
    float4 bb = ((const float4*)beta)[lane];
    float4 pm = make_float4(pv.x - mu, pv.y - mu, pv.z - mu, pv.w - mu);

    for (int q0 = beg; q0 < end; q0 += 32) {
        int cnt = end - q0 < 32 ? end - q0 : 32;
        int e = 0;
        float s = 0.f;
        if (lane < cnt) {
            e = g_permS[q0 + lane];
            s = snorm[e];
        }
        for (int qq = 0; qq < cnt; qq++) {
            int eq = __shfl_sync(0xffffffffu, e, qq);
            float sq = __shfl_sync(0xffffffffu, s, qq);
            float ts = sq * rsqrtf(var * sq * sq + 1e-5f);
            float4 o4;
            o4.x = fmaxf(pm.x * ts * gg.x + bb.x, 0.f);
            o4.y = fmaxf(pm.y * ts * gg.y + bb.y, 0.f);
            o4.z = fmaxf(pm.z * ts * gg.z + bb.z, 0.f);
            o4.w = fmaxf(pm.w * ts * gg.w + bb.w, 0.f);
            ((float4*)(out + (size_t)eq * 128))[lane] = o4;
        }
    }
}

// ---------------------------------------------------------------------------
extern "C" void kernel_launch(void* const* d_in, const int* in_sizes, int n_in,
                              void* d_out, int out_size) {
    const float* x = (const float*)d_in[0];
    const float* h = (const float*)d_in[1];
    const float* snorm_n = (const float*)d_in[2];
    const float* W1 = (const float*)d_in[4];
    const float* W2 = (const float*)d_in[5];
    const float* gamma = (const float*)d_in[6];
    const float* beta = (const float*)d_in[7];
    const int* src = (const int*)d_in[8];
    const int* dst = (const int*)d_in[9];
    float* out = (float*)d_out;

    cudaFuncSetAttribute(k_xab_h, cudaFuncAttributeMaxDynamicSharedMemorySize, NODE_SMEM);
    cudaFuncSetAttribute(k_p_h, cudaFuncAttributeMaxDynamicSharedMemorySize, NODE_SMEM);
    cudaFuncSetAttribute(k_edge, cudaFuncAttributeMaxDynamicSharedMemorySize, EDGE_SMEM);

    void* mnode;
    void* hist;
    cudaGetSymbolAddress(&mnode, g_mnode);
    cudaGetSymbolAddress(&hist, g_hist);

    cudaMemsetAsync(mnode, 0, (size_t)NN * 128 * 4);
    cudaMemsetAsync(hist, 0, 2 * NN * 4);
    k_hist<<<2500, 256>>>(dst, src);
    k_scan_local<<<dim3(40, 2), 1024>>>();
    k_scan_bsum<<<1, 128>>>();
    k_scan_add<<<dim3(40, 2), 1024>>>();
    k_scatter<<<2500, 256>>>(dst, src);
    k_xab_h<<<dim3(313, 2), 256, NODE_SMEM>>>(x, W1);
    k_edge<<<296, 256, EDGE_SMEM>>>(h, W1);
    k_p_h<<<313, 256, NODE_SMEM>>>(W2);
    k_ln_node<<<5000, 256>>>(snorm_n, gamma, beta, out);
}

// round 16
// speedup vs baseline: 1.0505x; 1.0505x over previous
#include <cuda_runtime.h>
#include <cstdint>

// ---------------------------------------------------------------------------
// D_MPNNLayer on GB300 (sm_103a via compute_103 -> mma.sync)
// Round-14 kernels exactly (fp16 edge GEMM 64-edge tiles 2 CTAs/SM, tf32 node
// GEMMs, warp-per-node LN) + stream-fork overlap: preprocessing || k_xab.
// ---------------------------------------------------------------------------

constexpr int NN = 40000;
constexpr int NE = 640000;

constexpr int LDT = 132;
constexpr int TW = 128 * LDT;
constexpr int XAB_SMEM = (2 * TW) * 4;

constexpr int LDH = 68;                 // f16x2 words per row
constexpr int BW = 128 * LDH;           // B tile words
constexpr int AW = 64 * LDH;            // A tile words (64 edges)
constexpr int EDGE_SMEM = (BW + 3 * AW) * 4 + 3 * 512;

__device__ float g_xab[(size_t)NN * 256];
__device__ float g_mnode[(size_t)NN * 128];
__device__ float g_p[(size_t)NN * 128];

__device__ int g_hist[2 * NN];
__device__ int g_workD[NN], g_workS[NN];
__device__ int g_startD[NN + 8], g_startS[NN + 8];
__device__ int g_bsum[80];
__device__ int g_permD[NE], g_permS[NE];
__device__ int g_sdstD[NE], g_ssrcD[NE];

__device__ __host__ __forceinline__ int permL(int r) {
    return (r & 0x61) | ((r >> 2) & 0x02) | ((r & 0x06) << 1) | (r & 0x10);
}
__device__ __forceinline__ int permE(int r) {
    return (r & 0x60) | (((r >> 1) & 3) << 3) | (((r >> 3) & 3) << 1) | (r & 1);
}

// ---------------- helpers ----------------------------------------------------
__device__ __forceinline__ uint32_t cvt_tf32(float f) {
    uint32_t r;
    asm("cvt.rna.tf32.f32 %0, %1;" : "=r"(r) : "f"(f));
    return r;
}
__device__ __forceinline__ uint32_t pk_f16x2(float lo, float hi) {
    uint32_t r;
    asm("cvt.rn.f16x2.f32 %0, %1, %2;" : "=r"(r) : "f"(hi), "f"(lo));
    return r;
}
__device__ __forceinline__ void mma8(float acc[4], uint32_t a0, uint32_t a1, uint32_t a2,
                                     uint32_t a3, uint32_t b0, uint32_t b1) {
    asm("mma.sync.aligned.m16n8k8.row.col.f32.tf32.tf32.f32 "
        "{%0,%1,%2,%3}, {%4,%5,%6,%7}, {%8,%9}, {%0,%1,%2,%3};"
        : "+f"(acc[0]), "+f"(acc[1]), "+f"(acc[2]), "+f"(acc[3])
        : "r"(a0), "r"(a1), "r"(a2), "r"(a3), "r"(b0), "r"(b1));
}
__device__ __forceinline__ void mma16h(float acc[4], uint32_t a0, uint32_t a1, uint32_t a2,
                                       uint32_t a3, uint32_t b0, uint32_t b1) {
    asm("mma.sync.aligned.m16n8k16.row.col.f32.f16.f16.f32 "
        "{%0,%1,%2,%3}, {%4,%5,%6,%7}, {%8,%9}, {%0,%1,%2,%3};"
        : "+f"(acc[0]), "+f"(acc[1]), "+f"(acc[2]), "+f"(acc[3])
        : "r"(a0), "r"(a1), "r"(a2), "r"(a3), "r"(b0), "r"(b1));
}
__device__ __forceinline__ void redv4(float* p, float4 v) {
    asm volatile("red.global.add.v4.f32 [%0], {%1,%2,%3,%4};" ::"l"(p), "f"(v.x), "f"(v.y),
                 "f"(v.z), "f"(v.w)
                 : "memory");
}
__device__ __forceinline__ void stage_quarter_f16(uint32_t* S, int row, int sq,
                                                  const float* __restrict__ gp) {
    uint32_t w[16];
#pragma unroll
    for (int i = 0; i < 8; i++) {
        float4 v = *(const float4*)(gp + i * 4);
        w[2 * i] = pk_f16x2(v.x, v.y);
        w[2 * i + 1] = pk_f16x2(v.z, v.w);
    }
    uint4* dp = (uint4*)(S + row * LDH + sq * 16);
#pragma unroll
    for (int j = 0; j < 4; j++) dp[j] = ((uint4*)w)[j];
}

template <int NT, bool PERM>
__device__ __forceinline__ void stage128_tf32(uint32_t* S, const float* __restrict__ g,
                                              int gstride, int nrows) {
#pragma unroll
    for (int i = 0; i < 4096 / NT; i++) {
        int idx = threadIdx.x + i * NT;
        int r = idx >> 5, k4 = idx & 31;
        int rl = PERM ? permL(r) : r;
        float4 v = make_float4(0.f, 0.f, 0.f, 0.f);
        if (rl < nrows) v = *(const float4*)(g + (size_t)rl * gstride + k4 * 4);
        uint4 w;
        w.x = cvt_tf32(v.x); w.y = cvt_tf32(v.y);
        w.z = cvt_tf32(v.z); w.w = cvt_tf32(v.w);
        *(uint4*)(S + r * LDT + k4 * 4) = w;
    }
}

// ---------------- preprocessing -----------------------------------------------
__global__ void k_hist(const int* __restrict__ dst, const int* __restrict__ src) {
    int e = blockIdx.x * 256 + threadIdx.x;
    atomicAdd(&g_hist[dst[e]], 1);
    atomicAdd(&g_hist[NN + src[e]], 1);
}
__global__ void __launch_bounds__(1024) k_scan_local() {
    __shared__ int sc[1024];
    int gy = blockIdx.y, bx = blockIdx.x, tid = threadIdx.x;
    int base = bx * 1000;
    const int* hist = g_hist + gy * NN;
    int* start = gy ? g_startS : g_startD;
    int v = (tid < 1000) ? hist[base + tid] : 0;
    sc[tid] = v;
    __syncthreads();
#pragma unroll
    for (int off = 1; off < 1024; off <<= 1) {
        int t = (tid >= off) ? sc[tid - off] : 0;
        __syncthreads();
        sc[tid] += t;
        __syncthreads();
    }
    if (tid < 1000) start[base + tid] = sc[tid] - v;
    if (tid == 1023) g_bsum[gy * 40 + bx] = sc[1023];
}
__global__ void __launch_bounds__(128) k_scan_bsum() {
    __shared__ int sc[128];
    int tid = threadIdx.x;
    int half = tid >> 6, loc = tid & 63;
    int v = (loc < 40) ? g_bsum[half * 40 + loc] : 0;
    sc[tid] = v;
    __syncthreads();
#pragma unroll
    for (int off = 1; off < 64; off <<= 1) {
        int t = (loc >= off) ? sc[tid - off] : 0;
        __syncthreads();
        sc[tid] += t;
        __syncthreads();
    }
    if (loc < 40) g_bsum[half * 40 + loc] = sc[tid] - v;
    if (loc == 63) {
        if (half == 0) g_startD[NN] = sc[tid];
        else g_startS[NN] = sc[tid];
    }
}
__global__ void __launch_bounds__(1024) k_scan_add() {
    int gy = blockIdx.y, bx = blockIdx.x, tid = threadIdx.x;
    if (tid >= 1000) return;
    int base = bx * 1000;
    int* start = gy ? g_startS : g_startD;
    int* work = gy ? g_workS : g_workD;
    int v = start[base + tid] + g_bsum[gy * 40 + bx];
    start[base + tid] = v;
    work[base + tid] = v;
}
__global__ void k_scatter(const int* __restrict__ dst, const int* __restrict__ src) {
    int e = blockIdx.x * 256 + threadIdx.x;
    int d = dst[e], s = src[e];
    int pd = atomicAdd(&g_workD[d], 1);
    g_permD[pd] = e;
    g_sdstD[pd] = d;
    g_ssrcD[pd] = s;
    int ps = atomicAdd(&g_workS[s], 1);
    g_permS[ps] = e;
}

// ---------------- tf32 node mma core -------------------------------------------
__device__ __forceinline__ void mma_core_256(const uint32_t* __restrict__ As,
                                             const uint32_t* __restrict__ Bs, int lane,
                                             int wm, int wn, float acc[2][8][4]) {
    int g = lane >> 2, tt = lane & 3;
    const uint32_t* ab = As + (wm * 32 + g) * LDT + tt;
    const uint32_t* bb = Bs + (wn * 64 + g) * LDT + tt;
#pragma unroll
    for (int ks = 0; ks < 16; ks++) {
        int k0 = ks * 8;
        uint32_t b[8][2];
#pragma unroll
        for (int nt = 0; nt < 8; nt++) {
            b[nt][0] = bb[nt * 8 * LDT + k0];
            b[nt][1] = bb[nt * 8 * LDT + k0 + 4];
        }
#pragma unroll
        for (int mt = 0; mt < 2; mt++) {
            uint32_t a0 = ab[(mt * 16 + 0) * LDT + k0];
            uint32_t a1 = ab[(mt * 16 + 8) * LDT + k0];
            uint32_t a2 = ab[(mt * 16 + 0) * LDT + k0 + 4];
            uint32_t a3 = ab[(mt * 16 + 8) * LDT + k0 + 4];
#pragma unroll
            for (int nt = 0; nt < 8; nt++) mma8(acc[mt][nt], a0, a1, a2, a3, b[nt][0], b[nt][1]);
        }
    }
}

__global__ void __launch_bounds__(256, 1) k_xab_mma(const float* __restrict__ x,
                                                    const float* __restrict__ W1) {
    extern __shared__ uint32_t sm[];
    uint32_t* Bs = sm;
    uint32_t* As = sm + TW;
    int lane = threadIdx.x & 31, wid = threadIdx.x >> 5;
    int wm = wid & 3, wn = wid >> 2;
    int half = blockIdx.y;
    int m0 = blockIdx.x * 128;
    int nrows = NN - m0 < 128 ? NN - m0 : 128;

    stage128_tf32<256, true>(Bs, W1 + half * 128, 384, 128);
    stage128_tf32<256, false>(As, x + (size_t)m0 * 128, 128, nrows);
    __syncthreads();

    float acc[2][8][4] = {};
    mma_core_256(As, Bs, lane, wm, wn, acc);

    int g = lane >> 2, tt = lane & 3;
#pragma unroll
    for (int mt = 0; mt < 2; mt++)
#pragma unroll
        for (int i = 0; i < 2; i++) {
            int r = m0 + wm * 32 + mt * 16 + g + i * 8;
            if (r < NN) {
                float* op = g_xab + (size_t)r * 256 + half * 128;
#pragma unroll
                for (int nt = 0; nt < 8; nt++) {
                    int col = permL(wn * 64 + nt * 8 + tt * 2);
                    *(float2*)(op + col) =
                        make_float2(acc[mt][nt][2 * i], acc[mt][nt][2 * i + 1]);
                }
            }
        }
}

__global__ void __launch_bounds__(256, 1) k_p_mma(const float* __restrict__ W2) {
    extern __shared__ uint32_t sm[];
    uint32_t* Bs = sm;
    uint32_t* As = sm + TW;
    int lane = threadIdx.x & 31, wid = threadIdx.x >> 5;
    int wm = wid & 3, wn = wid >> 2;
    int m0 = blockIdx.x * 128;
    int nrows = NN - m0 < 128 ? NN - m0 : 128;

    stage128_tf32<256, false>(Bs, W2, 128, 128);
    stage128_tf32<256, false>(As, g_mnode + (size_t)m0 * 128, 128, nrows);
    __syncthreads();

    float acc[2][8][4] = {};
    mma_core_256(As, Bs, lane, wm, wn, acc);

    int g = lane >> 2, tt = lane & 3;
#pragma unroll
    for (int mt = 0; mt < 2; mt++)
#pragma unroll
        for (int i = 0; i < 2; i++) {
            int r = m0 + wm * 32 + mt * 16 + g + i * 8;
            if (r < NN) {
                float* op = g_p + (size_t)r * 128 + wn * 64 + tt * 2;
#pragma unroll
                for (int nt = 0; nt < 8; nt++)
                    *(float2*)(op + nt * 8) =
                        make_float2(acc[mt][nt][2 * i], acc[mt][nt][2 * i + 1]);
            }
        }
}

// ---------------- edge kernel: 64-edge tiles, 256 thr, 2 CTAs/SM ---------------
__global__ void __launch_bounds__(256, 2) k_edge(const float* __restrict__ h,
                                                 const float* __restrict__ W1) {
    extern __shared__ uint32_t sm[];
    uint32_t* Bs = sm;
    uint32_t* A[3] = {sm + BW, sm + BW + AW, sm + BW + 2 * AW};
    int* idxB = (int*)(sm + BW + 3 * AW);

    int tid = threadIdx.x, lane = tid & 31, wid = tid >> 5;
    int wm = wid & 1, wn = wid >> 1;
    int g = lane >> 2, tt = lane & 3;

    int srow = tid >> 2, sq = tid & 3;
    int sj = ((srow >> 5) << 5) + ((srow & 7) << 2) + ((srow >> 3) & 3);

#pragma unroll
    for (int i = 0; i < 2; i++) {
        int idx = tid + i * 256;
        int r = idx >> 2, q = idx & 3;
        stage_quarter_f16(Bs, r, q, W1 + (size_t)permE(r) * 384 + 256 + q * 32);
    }

    const int G = gridDim.x;
    const int T = (10000 - blockIdx.x + G - 1) / G;

#pragma unroll
    for (int pt = 0; pt < 2; pt++) {
        if (pt < T) {
            int e0 = (blockIdx.x + (size_t)pt * G) * 64;
            int edge = g_permD[e0 + sj];
            stage_quarter_f16(A[pt], srow, sq, h + (size_t)edge * 128 + sq * 32);
            if (tid < 16) ((int4*)(idxB + pt * 128))[tid] = ((const int4*)(g_sdstD + e0))[tid];
            else if (tid < 32)
                ((int4*)(idxB + pt * 128 + 64))[tid - 16] =
                    ((const int4*)(g_ssrcD + e0))[tid - 16];
        }
    }
    __syncthreads();

    int cur = 0;
    for (int t = 0; t < T; t++) {
        bool more2 = (t + 2 < T);
        int nxt2 = cur + 2 >= 3 ? cur - 1 : cur + 2;

        float pf[32];
        int4 pd4 = make_int4(0, 0, 0, 0), ps4 = make_int4(0, 0, 0, 0);
        if (more2) {
            int e0 = (blockIdx.x + (size_t)(t + 2) * G) * 64;
            int edge = g_permD[e0 + sj];
            const float4* hp = (const float4*)(h + (size_t)edge * 128 + sq * 32);
#pragma unroll
            for (int i = 0; i < 8; i++) ((float4*)pf)[i] = hp[i];
            if (tid < 16) pd4 = ((const int4*)(g_sdstD + e0))[tid];
            else if (tid < 32) ps4 = ((const int4*)(g_ssrcD + e0))[tid - 16];
        }

        float acc[2][4][4] = {};
        {
            const uint32_t* ab = A[cur] + (wm * 32 + g) * LDH + tt;
            const uint32_t* bb = Bs + (wn * 32 + g) * LDH + tt;
#pragma unroll
            for (int ks = 0; ks < 8; ks++) {
                int k0 = ks * 8;
                uint32_t b[4][2];
#pragma unroll
                for (int nt = 0; nt < 4; nt++) {
                    b[nt][0] = bb[nt * 8 * LDH + k0];
                    b[nt][1] = bb[nt * 8 * LDH + k0 + 4];
                }
#pragma unroll
                for (int mt = 0; mt < 2; mt++) {
                    uint32_t a0 = ab[(mt * 16 + 0) * LDH + k0];
                    uint32_t a1 = ab[(mt * 16 + 8) * LDH + k0];
                    uint32_t a2 = ab[(mt * 16 + 0) * LDH + k0 + 4];
                    uint32_t a3 = ab[(mt * 16 + 8) * LDH + k0 + 4];
#pragma unroll
                    for (int nt = 0; nt < 4; nt++)
                        mma16h(acc[mt][nt], a0, a1, a2, a3, b[nt][0], b[nt][1]);
                }
            }
        }

        int jb = wm * 32 + 4 * g;
        int4 dd = *(const int4*)(idxB + cur * 128 + jb);
        int4 ss = *(const int4*)(idxB + cur * 128 + 64 + jb);

        if (more2) {
            uint32_t w[16];
#pragma unroll
            for (int j = 0; j < 16; j++) w[j] = pk_f16x2(pf[2 * j], pf[2 * j + 1]);
            uint4* dp = (uint4*)(A[nxt2] + srow * LDH + sq * 16);
#pragma unroll
            for (int j = 0; j < 4; j++) dp[j] = ((uint4*)w)[j];
            if (tid < 16) ((int4*)(idxB + nxt2 * 128))[tid] = pd4;
            else if (tid < 32) ((int4*)(idxB + nxt2 * 128 + 64))[tid - 16] = ps4;
        }

        int col0 = wn * 32 + tt * 8;
        int de[4] = {dd.x, dd.y, dd.z, dd.w};
        int se[4] = {ss.x, ss.y, ss.z, ss.w};
        float4 Bx[4][2];
#pragma unroll
        for (int c = 0; c < 4; c++) {
            const float* xb = g_xab + (size_t)se[c] * 256 + 128 + col0;
            Bx[c][0] = *(const float4*)xb;
            Bx[c][1] = *(const float4*)(xb + 4);
        }
        int curd = de[0];
        const float* xa = g_xab + (size_t)curd * 256 + col0;
        float4 A0 = *(const float4*)xa;
        float4 A1 = *(const float4*)(xa + 4);
        float4 ac0 = make_float4(0.f, 0.f, 0.f, 0.f);
        float4 ac1 = make_float4(0.f, 0.f, 0.f, 0.f);
#pragma unroll
        for (int c = 0; c < 4; c++) {
            if (de[c] != curd) {
                float* mp = g_mnode + (size_t)curd * 128 + col0;
                redv4(mp, ac0);
                redv4(mp + 4, ac1);
                curd = de[c];
                const float* xn = g_xab + (size_t)curd * 256 + col0;
                A0 = *(const float4*)xn;
                A1 = *(const float4*)(xn + 4);
                ac0 = make_float4(0.f, 0.f, 0.f, 0.f);
                ac1 = make_float4(0.f, 0.f, 0.f, 0.f);
            }
            int mt = c >> 1, i2 = (c & 1) * 2;
            ac0.x += fmaxf(acc[mt][0][i2] + A0.x + Bx[c][0].x, 0.f);
            ac0.y += fmaxf(acc[mt][0][i2 + 1] + A0.y + Bx[c][0].y, 0.f);
            ac0.z += fmaxf(acc[mt][1][i2] + A0.z + Bx[c][0].z, 0.f);
            ac0.w += fmaxf(acc[mt][1][i2 + 1] + A0.w + Bx[c][0].w, 0.f);
            ac1.x += fmaxf(acc[mt][2][i2] + A1.x + Bx[c][1].x, 0.f);
            ac1.y += fmaxf(acc[mt][2][i2 + 1] + A1.y + Bx[c][1].y, 0.f);
            ac1.z += fmaxf(acc[mt][3][i2] + A1.z + Bx[c][1].z, 0.f);
            ac1.w += fmaxf(acc[mt][3][i2 + 1] + A1.w + Bx[c][1].w, 0.f);
        }
        {
            float* mp = g_mnode + (size_t)curd * 128 + col0;
            redv4(mp, ac0);
            redv4(mp + 4, ac1);
        }

        cur = (cur + 1 >= 3) ? 0 : cur + 1;
        __syncthreads();
    }
}

// ---------------- LN: warp per node, parallel index/snorm loads ----------------
__global__ void __launch_bounds__(256) k_ln_node(const float* __restrict__ snorm,
                                                 const float* __restrict__ gamma,
                                                 const float* __restrict__ beta,
                                                 float* __restrict__ out) {
    int wid = threadIdx.x >> 5, lane = threadIdx.x & 31;
    int v = blockIdx.x * 8 + wid;
    int beg = g_startS[v], end = g_startS[v + 1];
    if (beg == end) return;

    float4 pv = ((const float4*)(g_p + (size_t)v * 128))[lane];
    float sum = pv.x + pv.y + pv.z + pv.w;
    float ssq = pv.x * pv.x + pv.y * pv.y + pv.z * pv.z + pv.w * pv.w;
#pragma unroll
    for (int o = 16; o > 0; o >>= 1) {
        sum += __shfl_xor_sync(0xffffffffu, sum, o);
        ssq += __shfl_xor_sync(0xffffffffu, ssq, o);
    }
    float mu = sum * 0.0078125f;
    float var = ssq * 0.0078125f - mu * mu;
    float4 gg = ((const float4*)gamma)[lane];
    float4 bb = ((const float4*)beta)[lane];
    float4 pm = make_float4(pv.x - mu, pv.y - mu, pv.z - mu, pv.w - mu);

    for (int q0 = beg; q0 < end; q0 += 32) {
        int cnt = end - q0 < 32 ? end - q0 : 32;
        int e = 0;
        float s = 0.f;
        if (lane < cnt) {
            e = g_permS[q0 + lane];
            s = snorm[e];
        }
        for (int qq = 0; qq < cnt; qq++) {
            int eq = __shfl_sync(0xffffffffu, e, qq);
            float sq = __shfl_sync(0xffffffffu, s, qq);
            float ts = sq * rsqrtf(var * sq * sq + 1e-5f);
            float4 o4;
            o4.x = fmaxf(pm.x * ts * gg.x + bb.x, 0.f);
            o4.y = fmaxf(pm.y * ts * gg.y + bb.y, 0.f);
            o4.z = fmaxf(pm.z * ts * gg.z + bb.z, 0.f);
            o4.w = fmaxf(pm.w * ts * gg.w + bb.w, 0.f);
            ((float4*)(out + (size_t)eq * 128))[lane] = o4;
        }
    }
}

// ---------------------------------------------------------------------------
extern "C" void kernel_launch(void* const* d_in, const int* in_sizes, int n_in,
                              void* d_out, int out_size) {
    const float* x = (const float*)d_in[0];
    const float* h = (const float*)d_in[1];
    const float* snorm_n = (const float*)d_in[2];
    const float* W1 = (const float*)d_in[4];
    const float* W2 = (const float*)d_in[5];
    const float* gamma = (const float*)d_in[6];
    const float* beta = (const float*)d_in[7];
    const int* src = (const int*)d_in[8];
    const int* dst = (const int*)d_in[9];
    float* out = (float*)d_out;

    static cudaStream_t s2 = nullptr;
    static cudaEvent_t evFork = nullptr, evJoin = nullptr;
    if (s2 == nullptr) {
        cudaStreamCreateWithFlags(&s2, cudaStreamNonBlocking);
        cudaEventCreateWithFlags(&evFork, cudaEventDisableTiming);
        cudaEventCreateWithFlags(&evJoin, cudaEventDisableTiming);
        cudaFuncSetAttribute(k_xab_mma, cudaFuncAttributeMaxDynamicSharedMemorySize, XAB_SMEM);
        cudaFuncSetAttribute(k_p_mma, cudaFuncAttributeMaxDynamicSharedMemorySize, XAB_SMEM);
        cudaFuncSetAttribute(k_edge, cudaFuncAttributeMaxDynamicSharedMemorySize, EDGE_SMEM);
    }

    void* mnode;
    void* hist;
    cudaGetSymbolAddress(&mnode, g_mnode);
    cudaGetSymbolAddress(&hist, g_hist);

    // fork: preprocessing on s2, xab + mnode memset on origin stream
    cudaEventRecord(evFork, 0);
    cudaStreamWaitEvent(s2, evFork, 0);

    // s2: sort preprocessing chain
    cudaMemsetAsync(hist, 0, 2 * NN * 4, s2);
    k_hist<<<2500, 256, 0, s2>>>(dst, src);
    k_scan_local<<<dim3(40, 2), 1024, 0, s2>>>();
    k_scan_bsum<<<1, 128, 0, s2>>>();
    k_scan_add<<<dim3(40, 2), 1024, 0, s2>>>();
    k_scatter<<<2500, 256, 0, s2>>>(dst, src);

    // origin: mnode zero + node GEMM
    cudaMemsetAsync(mnode, 0, (size_t)NN * 128 * 4);
    k_xab_mma<<<dim3(313, 2), 256, XAB_SMEM>>>(x, W1);

    // join
    cudaEventRecord(evJoin, s2);
    cudaStreamWaitEvent(0, evJoin, 0);

    k_edge<<<296, 256, EDGE_SMEM>>>(h, W1);
    k_p_mma<<<313, 256, XAB_SMEM>>>(W2);
    k_ln_node<<<5000, 256>>>(snorm_n, gamma, beta, out);
}